// round 1
// baseline (speedup 1.0000x reference)
#include <cuda_runtime.h>
#include <cuda_bf16.h>

// Problem constants
#define BATCH 4
#define TLEN  4096
#define DIM   1024
#define NH    16
#define HD    64

// Scratch (device globals; no allocation allowed)
__device__ static float g_kv[BATCH * TLEN * 2 * DIM];   // 128 MB: k|v, k overwritten with exp(k-max)
__device__ static float g_q [BATCH * TLEN * DIM];       // 64 MB
__device__ static float g_Z [BATCH * DIM];              // softmax denominators per (b, col)
__device__ static float g_Cn[BATCH * NH * HD * HD];     // normalized context
__device__ static float g_E [BATCH * DIM * DIM];        // E_b = blockdiag(Cn) @ W_out

// ---------------------------------------------------------------------------
// Generic batched SGEMM: C = A[MxK] * B[KxN] + bias, row-major, 128x128x8 tile
// ---------------------------------------------------------------------------
#define BM 128
#define BN 128
#define BKK 8
#define TM 8
#define TN 8

__global__ __launch_bounds__(256)
void sgemm_bias(const float* __restrict__ A, const float* __restrict__ B,
                const float* __restrict__ bias, float* __restrict__ C,
                int M, int N, int K,
                long sA, long sB, long sC)
{
    const int bz = blockIdx.z;
    A += (long)bz * sA; B += (long)bz * sB; C += (long)bz * sC;

    const int brow = blockIdx.y * BM;
    const int bcol = blockIdx.x * BN;

    __shared__ float As[BKK][BM];
    __shared__ float Bs[BKK][BN];

    const int tid = threadIdx.x;
    const int aRow = tid >> 1;            // 0..127
    const int aK   = (tid & 1) * 4;       // 0 or 4
    const int bRow = tid >> 5;            // 0..7
    const int bCol = (tid & 31) * 4;      // 0..124

    const int ty = tid >> 4;              // 0..15
    const int tx = tid & 15;              // 0..15

    float acc[TM][TN];
#pragma unroll
    for (int i = 0; i < TM; i++)
#pragma unroll
        for (int j = 0; j < TN; j++) acc[i][j] = 0.f;

    for (int k0 = 0; k0 < K; k0 += BKK) {
        float4 a4 = *(const float4*)(A + (long)(brow + aRow) * K + k0 + aK);
        As[aK + 0][aRow] = a4.x;
        As[aK + 1][aRow] = a4.y;
        As[aK + 2][aRow] = a4.z;
        As[aK + 3][aRow] = a4.w;
        *(float4*)&Bs[bRow][bCol] =
            *(const float4*)(B + (long)(k0 + bRow) * N + bcol + bCol);
        __syncthreads();

#pragma unroll
        for (int kk = 0; kk < BKK; kk++) {
            float ra[TM], rb[TN];
            float4 b0 = *(float4*)&Bs[kk][tx * TN];
            float4 b1 = *(float4*)&Bs[kk][tx * TN + 4];
            rb[0] = b0.x; rb[1] = b0.y; rb[2] = b0.z; rb[3] = b0.w;
            rb[4] = b1.x; rb[5] = b1.y; rb[6] = b1.z; rb[7] = b1.w;
#pragma unroll
            for (int i = 0; i < TM; i++) ra[i] = As[kk][ty * TM + i];
#pragma unroll
            for (int i = 0; i < TM; i++)
#pragma unroll
                for (int j = 0; j < TN; j++)
                    acc[i][j] = fmaf(ra[i], rb[j], acc[i][j]);
        }
        __syncthreads();
    }

#pragma unroll
    for (int i = 0; i < TM; i++) {
        const int r = brow + ty * TM + i;
#pragma unroll
        for (int j = 0; j < TN; j += 4) {
            const int c = bcol + tx * TN + j;
            float4 o;
            o.x = acc[i][j + 0] + bias[c + 0];
            o.y = acc[i][j + 1] + bias[c + 1];
            o.z = acc[i][j + 2] + bias[c + 2];
            o.w = acc[i][j + 3] + bias[c + 3];
            *(float4*)(C + (long)r * N + c) = o;
        }
    }
}

// ---------------------------------------------------------------------------
// Column softmax over the time axis of k (first DIM columns of g_kv).
// Writes exp(x - max) in place, stores column sums Z (normalization is folded
// into the context kernel).
// grid = BATCH * (DIM/32); block = 256 (32 cols x 8 row-groups)
// ---------------------------------------------------------------------------
__global__ __launch_bounds__(256)
void softmax_time_kernel()
{
    const int b = blockIdx.x >> 5;                 // /32
    const int colbase = (blockIdx.x & 31) * 32;
    const int lane = threadIdx.x & 31;
    const int grp  = threadIdx.x >> 5;             // 0..7
    const int col  = colbase + lane;

    float* base = g_kv + (long)b * TLEN * (2 * DIM) + col;

    __shared__ float red[8][32];

    float m = -3.402823466e38f;
    for (int t = grp; t < TLEN; t += 8)
        m = fmaxf(m, base[(long)t * (2 * DIM)]);
    red[grp][lane] = m;
    __syncthreads();
    if (grp == 0) {
        float mm = red[0][lane];
#pragma unroll
        for (int g = 1; g < 8; g++) mm = fmaxf(mm, red[g][lane]);
        red[0][lane] = mm;
    }
    __syncthreads();
    m = red[0][lane];
    __syncthreads();

    float s = 0.f;
    for (int t = grp; t < TLEN; t += 8) {
        const long off = (long)t * (2 * DIM);
        float e = expf(base[off] - m);
        base[off] = e;
        s += e;
    }
    red[grp][lane] = s;
    __syncthreads();
    if (grp == 0) {
        float ss = red[0][lane];
#pragma unroll
        for (int g = 1; g < 8; g++) ss += red[g][lane];
        g_Z[b * DIM + col] = ss;
    }
}

// ---------------------------------------------------------------------------
// Context per (b,h): Cn[d][w] = (1/Z[d]) * sum_t ek[t,d] * v[t,w]   (64x64)
// grid = BATCH*NH; block = 256 (16x16 threads, 4x4 micro-tile), T chunked by 32
// ---------------------------------------------------------------------------
__global__ __launch_bounds__(256)
void context_kernel()
{
    const int bh = blockIdx.x;
    const int b = bh >> 4;
    const int h = bh & 15;

    const float* kbase = g_kv + (long)b * TLEN * (2 * DIM) + h * HD;
    const float* vbase = kbase + DIM;

    __shared__ float ks[32][68];   // padded stride (68*4 = 272 B, 16B aligned)
    __shared__ float vs[32][68];

    const int tid = threadIdx.x;
    const int tx = tid & 15;
    const int ty = tid >> 4;

    float acc[4][4];
#pragma unroll
    for (int i = 0; i < 4; i++)
#pragma unroll
        for (int j = 0; j < 4; j++) acc[i][j] = 0.f;

    for (int t0 = 0; t0 < TLEN; t0 += 32) {
        for (int i = tid; i < 512; i += 256) {
            const int r  = i >> 4;
            const int c4 = (i & 15) * 4;
            *(float4*)&ks[r][c4] = *(const float4*)(kbase + (long)(t0 + r) * (2 * DIM) + c4);
            *(float4*)&vs[r][c4] = *(const float4*)(vbase + (long)(t0 + r) * (2 * DIM) + c4);
        }
        __syncthreads();
#pragma unroll 8
        for (int kk = 0; kk < 32; kk++) {
            float rd[4], rv[4];
#pragma unroll
            for (int i = 0; i < 4; i++) rd[i] = ks[kk][ty * 4 + i];
#pragma unroll
            for (int j = 0; j < 4; j++) rv[j] = vs[kk][tx * 4 + j];
#pragma unroll
            for (int i = 0; i < 4; i++)
#pragma unroll
                for (int j = 0; j < 4; j++)
                    acc[i][j] = fmaf(rd[i], rv[j], acc[i][j]);
        }
        __syncthreads();
    }

    float* out = g_Cn + (long)bh * HD * HD;
#pragma unroll
    for (int i = 0; i < 4; i++) {
        const int d = ty * 4 + i;
        const float invz = 1.f / g_Z[b * DIM + h * HD + d];
#pragma unroll
        for (int j = 0; j < 4; j++)
            out[d * HD + tx * 4 + j] = acc[i][j] * invz;
    }
}

// ---------------------------------------------------------------------------
// Expand: E_b[h*64+d][n] = sum_w Cn[b,h][d][w] * W_out[h*64+w][n]
// grid = (DIM/128, BATCH*NH); block = 256
// ---------------------------------------------------------------------------
__global__ __launch_bounds__(256)
void expand_kernel(const float* __restrict__ w_out)
{
    const int bh = blockIdx.y;
    const int b = bh >> 4;
    const int h = bh & 15;
    const int cb = blockIdx.x * 128;

    __shared__ float cs[64][64];     // Cn  (16 KB)
    __shared__ float ws[64][128];    // W slice (32 KB)

    const int tid = threadIdx.x;
    for (int i = tid; i < 1024; i += 256) {
        const int r = i >> 4;
        const int c = (i & 15) * 4;
        *(float4*)&cs[r][c] = *(const float4*)(g_Cn + (long)bh * 4096 + r * 64 + c);
    }
    for (int i = tid; i < 2048; i += 256) {
        const int r = i >> 5;
        const int c = (i & 31) * 4;
        *(float4*)&ws[r][c] = *(const float4*)(w_out + (long)(h * HD + r) * DIM + cb + c);
    }
    __syncthreads();

    const int tx = tid & 31;   // col group: cols tx*4 .. tx*4+3
    const int ty = tid >> 5;   // row offset 0..7; rows ty + 8*rr

    float acc[8][4];
#pragma unroll
    for (int rr = 0; rr < 8; rr++)
#pragma unroll
        for (int j = 0; j < 4; j++) acc[rr][j] = 0.f;

#pragma unroll 4
    for (int w = 0; w < 64; w++) {
        float4 wv = *(float4*)&ws[w][tx * 4];
#pragma unroll
        for (int rr = 0; rr < 8; rr++) {
            const float cv = cs[ty + rr * 8][w];
            acc[rr][0] = fmaf(cv, wv.x, acc[rr][0]);
            acc[rr][1] = fmaf(cv, wv.y, acc[rr][1]);
            acc[rr][2] = fmaf(cv, wv.z, acc[rr][2]);
            acc[rr][3] = fmaf(cv, wv.w, acc[rr][3]);
        }
    }

#pragma unroll
    for (int rr = 0; rr < 8; rr++) {
        const int row = ty + rr * 8;
        float4 o; o.x = acc[rr][0]; o.y = acc[rr][1]; o.z = acc[rr][2]; o.w = acc[rr][3];
        *(float4*)(g_E + ((long)b * DIM + h * HD + row) * DIM + cb + tx * 4) = o;
    }
}

// ---------------------------------------------------------------------------
extern "C" void kernel_launch(void* const* d_in, const int* in_sizes, int n_in,
                              void* d_out, int out_size)
{
    const float* x     = (const float*)d_in[0];
    const float* z     = (const float*)d_in[1];
    const float* w_q   = (const float*)d_in[2];
    const float* b_q   = (const float*)d_in[3];
    const float* w_kv  = (const float*)d_in[4];
    const float* b_kv  = (const float*)d_in[5];
    const float* w_out = (const float*)d_in[6];
    const float* b_out = (const float*)d_in[7];
    float* out = (float*)d_out;

    float *kv, *q, *E;
    cudaGetSymbolAddress((void**)&kv, g_kv);
    cudaGetSymbolAddress((void**)&q,  g_q);
    cudaGetSymbolAddress((void**)&E,  g_E);

    const int M = BATCH * TLEN;   // 16384

    // 1. kv = z @ w_kv + b_kv   [16384 x 2048]
    {
        dim3 grid(2 * DIM / BN, M / BM, 1);
        sgemm_bias<<<grid, 256>>>(z, w_kv, b_kv, kv, M, 2 * DIM, DIM, 0, 0, 0);
    }
    // 2. q = x @ w_q + b_q      [16384 x 1024]
    {
        dim3 grid(DIM / BN, M / BM, 1);
        sgemm_bias<<<grid, 256>>>(x, w_q, b_q, q, M, DIM, DIM, 0, 0, 0);
    }
    // 3. softmax over time on k (in place, Z saved)
    softmax_time_kernel<<<BATCH * (DIM / 32), 256>>>();
    // 4. per-head context (normalized)
    context_kernel<<<BATCH * NH, 256>>>();
    // 5. expand per-head context into E_b (folding w_out)
    {
        dim3 grid(DIM / 128, BATCH * NH);
        expand_kernel<<<grid, 256>>>(w_out);
    }
    // 6. out_b = q_b @ E_b + b_out   (batched over BATCH)
    {
        dim3 grid(DIM / BN, TLEN / BM, BATCH);
        sgemm_bias<<<grid, 256>>>(q, E, b_out, out, TLEN, DIM, DIM,
                                  (long)TLEN * DIM, (long)DIM * DIM, (long)TLEN * DIM);
    }
}

// round 3
// speedup vs baseline: 3.0085x; 3.0085x over previous
#include <cuda_runtime.h>
#include <cuda_bf16.h>
#include <cstdint>

// Problem constants
#define BATCH 4
#define TLEN  4096
#define DIM   1024
#define NH    16
#define HD    64
#define K3    3072           // split-bf16 K' = 3*DIM

// ---------------------------------------------------------------------------
// Scratch (device globals; no allocation allowed)
// ---------------------------------------------------------------------------
__device__ static __align__(256) float g_kv[BATCH * TLEN * 2 * DIM];   // 128 MB
__device__ static __align__(256) float g_Z [BATCH * DIM];
__device__ static __align__(256) float g_Cp[BATCH * NH * 8 * HD * HD];
__device__ static __align__(256) float g_Cn[BATCH * NH * HD * HD];
__device__ static __align__(256) float g_E [BATCH * DIM * DIM];        // 16 MB

__device__ static __align__(256) __nv_bfloat16 g_zs [(long)BATCH * TLEN * K3]; // 100.7 MB
__device__ static __align__(256) __nv_bfloat16 g_xs [(long)BATCH * TLEN * K3];
__device__ static __align__(256) __nv_bfloat16 g_qs [(long)BATCH * TLEN * K3];
__device__ static __align__(256) __nv_bfloat16 g_wkvs[(long)2 * DIM * K3];
__device__ static __align__(256) __nv_bfloat16 g_wqs [(long)DIM * K3];
__device__ static __align__(256) __nv_bfloat16 g_Es  [(long)BATCH * DIM * K3];

// ---------------------------------------------------------------------------
// Helpers
// ---------------------------------------------------------------------------
#define SW128(o) ((o) ^ (((o) >> 3) & 0x70))

static __device__ __forceinline__ uint32_t su32(const void* p) {
    uint32_t a;
    asm("{ .reg .u64 t; cvta.to.shared.u64 t, %1; cvt.u32.u64 %0, t; }" : "=r"(a) : "l"(p));
    return a;
}

#define CP16(dst, src)   asm volatile("cp.async.cg.shared.global [%0], [%1], 16;" :: "r"(dst), "l"(src))
#define CP_COMMIT()      asm volatile("cp.async.commit_group;" ::: "memory")
#define CP_WAIT(n)       asm volatile("cp.async.wait_group %0;" :: "n"(n) : "memory")

#define LDSM4(r0, r1, r2, r3, addr) \
    asm volatile("ldmatrix.sync.aligned.m8n8.x4.shared.b16 {%0,%1,%2,%3}, [%4];" \
        : "=r"(r0), "=r"(r1), "=r"(r2), "=r"(r3) : "r"(addr))

#define MMA16816(d, a, b) \
    asm volatile("mma.sync.aligned.m16n8k16.row.col.f32.bf16.bf16.f32 " \
        "{%0,%1,%2,%3},{%4,%5,%6,%7},{%8,%9},{%0,%1,%2,%3};" \
        : "+f"((d)[0]), "+f"((d)[1]), "+f"((d)[2]), "+f"((d)[3]) \
        : "r"((a)[0]), "r"((a)[1]), "r"((a)[2]), "r"((a)[3]), "r"((b)[0]), "r"((b)[1]))

// ---------------------------------------------------------------------------
// mma.sync bf16 GEMM:  C[M,N] = A'[M,K3] * B'[N,K3]^T + bias
// BM=128, BN=128, BK=64 (128B rows, SW128), 3-stage cp.async, 8 warps (2x4),
// warp tile 64x32. split=1: write split-bf16 [hi|lo|hi] rows of width K3.
// grid = (N/128, M/128, batch)
// ---------------------------------------------------------------------------
#define GNK   (K3 / 64)             // 48 k-tiles
#define NSTG  3
#define TILE_B 16384                // 128 rows x 128 B
#define STG_B  (2 * TILE_B)
#define GSMEM  (NSTG * STG_B)

extern __shared__ __align__(1024) char gsm_raw[];

__global__ __launch_bounds__(256)
void gemm_mma(const __nv_bfloat16* __restrict__ A, const __nv_bfloat16* __restrict__ B,
              const float* __restrict__ bias, float* __restrict__ Cf,
              __nv_bfloat16* __restrict__ Cs, int N, int split,
              long sA, long sB, long sC)
{
    A += blockIdx.z * sA; B += blockIdx.z * sB;
    const int m0 = blockIdx.y * 128;
    const int n0 = blockIdx.x * 128;
    const uint32_t sbase = su32(gsm_raw);
    const int tid = threadIdx.x, wid = tid >> 5, lane = tid & 31;

    const __nv_bfloat16* Arow = A + (long)m0 * K3;
    const __nv_bfloat16* Brow = B + (long)n0 * K3;

    auto load_tile = [&](int kt, int s) {
        const uint32_t sa = sbase + s * STG_B;
        const uint32_t sb = sa + TILE_B;
        const __nv_bfloat16* Ab = Arow + kt * 64;
        const __nv_bfloat16* Bb = Brow + kt * 64;
#pragma unroll
        for (int it = 0; it < 8; it++) {
            int i = tid + it * 256;              // 0..2047
            int row = i >> 3, ch = (i & 7) * 16; // byte chunk
            if (it < 4) CP16(sa + SW128(row * 128 + ch), Ab + (long)row * K3 + ch / 2);
            else {
                row -= 128;
                CP16(sb + SW128(row * 128 + ch), Bb + (long)row * K3 + ch / 2);
            }
        }
    };

    float acc[4][4][4];
#pragma unroll
    for (int mf = 0; mf < 4; mf++)
#pragma unroll
        for (int nf = 0; nf < 4; nf++)
#pragma unroll
            for (int r = 0; r < 4; r++) acc[mf][nf][r] = 0.f;

    const int wm = wid >> 2, wn = wid & 3;
    // ldmatrix lane-address components (byte offsets inside a tile)
    const int a_row = wm * 64 + (lane & 15);            // + mf*16
    const int a_sec = (lane >> 4) * 16;                 // k-halves
    const int b_row = wn * 32 + (lane & 7) + ((lane >> 4) << 3);  // + nf2*16
    const int b_sec = ((lane >> 3) & 1) * 16;

    load_tile(0, 0); CP_COMMIT();
    load_tile(1, 1); CP_COMMIT();

    for (int kt = 0; kt < GNK; kt++) {
        const int kn = kt + 2;
        if (kn < GNK) { load_tile(kn, kn % NSTG); CP_COMMIT(); CP_WAIT(2); }
        else if (kt == GNK - 2) CP_WAIT(1);
        else CP_WAIT(0);
        __syncthreads();

        const uint32_t sa = sbase + (kt % NSTG) * STG_B;
        const uint32_t sb = sa + TILE_B;
#pragma unroll
        for (int ks = 0; ks < 4; ks++) {
            uint32_t af[4][4], bf[4][2];
#pragma unroll
            for (int mf = 0; mf < 4; mf++)
                LDSM4(af[mf][0], af[mf][1], af[mf][2], af[mf][3],
                      sa + SW128((a_row + mf * 16) * 128 + ks * 32 + a_sec));
#pragma unroll
            for (int nf2 = 0; nf2 < 2; nf2++)
                LDSM4(bf[nf2 * 2][0], bf[nf2 * 2][1], bf[nf2 * 2 + 1][0], bf[nf2 * 2 + 1][1],
                      sb + SW128((b_row + nf2 * 16) * 128 + ks * 32 + b_sec));
#pragma unroll
            for (int mf = 0; mf < 4; mf++)
#pragma unroll
                for (int nf = 0; nf < 4; nf++)
                    MMA16816(acc[mf][nf], af[mf], bf[nf]);
        }
        __syncthreads();
    }

    // Epilogue: direct register -> global
#pragma unroll
    for (int mf = 0; mf < 4; mf++) {
        const int row = m0 + wm * 64 + mf * 16 + (lane >> 2);
#pragma unroll
        for (int nf = 0; nf < 4; nf++) {
            const int col = n0 + wn * 32 + nf * 8 + (lane & 3) * 2;
            const float b0 = __ldg(bias + col), b1 = __ldg(bias + col + 1);
            float v0 = acc[mf][nf][0] + b0, v1 = acc[mf][nf][1] + b1;
            float v2 = acc[mf][nf][2] + b0, v3 = acc[mf][nf][3] + b1;
            if (!split) {
                float* c0 = Cf + blockIdx.z * sC + (long)row * N + col;
                float2 p0; p0.x = v0; p0.y = v1; *(float2*)c0 = p0;
                float2 p1; p1.x = v2; p1.y = v3; *(float2*)(c0 + 8 * N) = p1;
            } else {
                // split-bf16 activation rows: [hi | lo | hi], width K3
                __nv_bfloat16 h0 = __float2bfloat16(v0), h1 = __float2bfloat16(v1);
                __nv_bfloat16 h2 = __float2bfloat16(v2), h3 = __float2bfloat16(v3);
                __nv_bfloat16 l0 = __float2bfloat16(v0 - __bfloat162float(h0));
                __nv_bfloat16 l1 = __float2bfloat16(v1 - __bfloat162float(h1));
                __nv_bfloat16 l2 = __float2bfloat16(v2 - __bfloat162float(h2));
                __nv_bfloat16 l3 = __float2bfloat16(v3 - __bfloat162float(h3));
                __nv_bfloat16* o0 = Cs + (long)row * K3 + col;
                __nv_bfloat16* o1 = Cs + (long)(row + 8) * K3 + col;
                __nv_bfloat162 p;
                p.x = h0; p.y = h1; *(__nv_bfloat162*)o0 = p; *(__nv_bfloat162*)(o0 + 2 * DIM) = p;
                p.x = l0; p.y = l1; *(__nv_bfloat162*)(o0 + DIM) = p;
                p.x = h2; p.y = h3; *(__nv_bfloat162*)o1 = p; *(__nv_bfloat162*)(o1 + 2 * DIM) = p;
                p.x = l2; p.y = l3; *(__nv_bfloat162*)(o1 + DIM) = p;
            }
        }
    }
}

// ---------------------------------------------------------------------------
// split-bf16 conversions
// ---------------------------------------------------------------------------
// Activations: [M,1024] f32 -> [M,3072] bf16 as [hi | lo | hi]
__global__ __launch_bounds__(256)
void split_act(const float* __restrict__ in, __nv_bfloat16* __restrict__ out, long total4)
{
    for (long idx = blockIdx.x * 256L + threadIdx.x; idx < total4; idx += gridDim.x * 256L) {
        float4 v = ((const float4*)in)[idx];
        long m = idx >> 8;
        int c = (int)(idx & 255) * 4;
        __nv_bfloat16 h0 = __float2bfloat16(v.x), h1 = __float2bfloat16(v.y);
        __nv_bfloat16 h2 = __float2bfloat16(v.z), h3 = __float2bfloat16(v.w);
        __nv_bfloat16 l0 = __float2bfloat16(v.x - __bfloat162float(h0));
        __nv_bfloat16 l1 = __float2bfloat16(v.y - __bfloat162float(h1));
        __nv_bfloat16 l2 = __float2bfloat16(v.z - __bfloat162float(h2));
        __nv_bfloat16 l3 = __float2bfloat16(v.w - __bfloat162float(h3));
        __nv_bfloat16* o = out + m * K3 + c;
        __nv_bfloat162 p;
        p.x = h0; p.y = h1; ((__nv_bfloat162*)o)[0] = p;
        p.x = h2; p.y = h3; ((__nv_bfloat162*)o)[1] = p;
        p.x = h0; p.y = h1; ((__nv_bfloat162*)(o + 2 * DIM))[0] = p;
        p.x = h2; p.y = h3; ((__nv_bfloat162*)(o + 2 * DIM))[1] = p;
        p.x = l0; p.y = l1; ((__nv_bfloat162*)(o + DIM))[0] = p;
        p.x = l2; p.y = l3; ((__nv_bfloat162*)(o + DIM))[1] = p;
    }
}

// Weights (transpose+split): in [1024,N] f32 -> out [N,3072] bf16 as [hi | hi | lo]
__global__ __launch_bounds__(256)
void split_wt(const float* __restrict__ in, __nv_bfloat16* __restrict__ out,
              int N, long sin, long sout)
{
    __shared__ float t[32][33];
    in += blockIdx.z * sin; out += blockIdx.z * sout;
    const int n0 = blockIdx.x * 32, k0 = blockIdx.y * 32;
    const int tx = threadIdx.x & 31, ty = threadIdx.x >> 5;
#pragma unroll
    for (int i = 0; i < 4; i++)
        t[ty + i * 8][tx] = in[(long)(k0 + ty + i * 8) * N + n0 + tx];
    __syncthreads();
#pragma unroll
    for (int i = 0; i < 4; i++) {
        const int nn = ty + i * 8;
        float v = t[tx][nn];
        __nv_bfloat16 hi = __float2bfloat16(v);
        __nv_bfloat16 lo = __float2bfloat16(v - __bfloat162float(hi));
        __nv_bfloat16* o = out + (long)(n0 + nn) * K3 + k0 + tx;
        o[0] = hi; o[DIM] = hi; o[2 * DIM] = lo;
    }
}

// ---------------------------------------------------------------------------
// Column softmax over time on the k half of g_kv (in place; Z saved)
// ---------------------------------------------------------------------------
__global__ __launch_bounds__(256)
void softmax_time_kernel()
{
    const int b = blockIdx.x >> 5;
    const int colbase = (blockIdx.x & 31) * 32;
    const int lane = threadIdx.x & 31;
    const int grp = threadIdx.x >> 5;
    const int col = colbase + lane;

    float* base = g_kv + (long)b * TLEN * (2 * DIM) + col;
    __shared__ float red[8][32];

    float m = -3.402823466e38f;
    for (int t = grp; t < TLEN; t += 8)
        m = fmaxf(m, base[(long)t * (2 * DIM)]);
    red[grp][lane] = m;
    __syncthreads();
    if (grp == 0) {
        float mm = red[0][lane];
#pragma unroll
        for (int g = 1; g < 8; g++) mm = fmaxf(mm, red[g][lane]);
        red[0][lane] = mm;
    }
    __syncthreads();
    m = red[0][lane];
    __syncthreads();

    float s = 0.f;
    for (int t = grp; t < TLEN; t += 8) {
        const long off = (long)t * (2 * DIM);
        float e = expf(base[off] - m);
        base[off] = e;
        s += e;
    }
    red[grp][lane] = s;
    __syncthreads();
    if (grp == 0) {
        float ss = red[0][lane];
#pragma unroll
        for (int g = 1; g < 8; g++) ss += red[g][lane];
        g_Z[b * DIM + col] = ss;
    }
}

// ---------------------------------------------------------------------------
// Context partials + reduce (normalize by Z)
// ---------------------------------------------------------------------------
__global__ __launch_bounds__(256)
void context_part()
{
    const int bh = blockIdx.x;
    const int tc = blockIdx.y;
    const int b = bh >> 4;
    const int h = bh & 15;

    const float* kbase = g_kv + (long)b * TLEN * (2 * DIM) + h * HD;
    const float* vbase = kbase + DIM;

    __shared__ float ks[32][68];
    __shared__ float vs[32][68];

    const int tid = threadIdx.x;
    const int tx = tid & 15;
    const int ty = tid >> 4;

    float acc[4][4];
#pragma unroll
    for (int i = 0; i < 4; i++)
#pragma unroll
        for (int j = 0; j < 4; j++) acc[i][j] = 0.f;

    for (int t0 = tc * 512; t0 < tc * 512 + 512; t0 += 32) {
        for (int i = tid; i < 512; i += 256) {
            const int r = i >> 4;
            const int c4 = (i & 15) * 4;
            *(float4*)&ks[r][c4] = *(const float4*)(kbase + (long)(t0 + r) * (2 * DIM) + c4);
            *(float4*)&vs[r][c4] = *(const float4*)(vbase + (long)(t0 + r) * (2 * DIM) + c4);
        }
        __syncthreads();
#pragma unroll 8
        for (int kk = 0; kk < 32; kk++) {
            float rd[4], rv[4];
#pragma unroll
            for (int i = 0; i < 4; i++) rd[i] = ks[kk][ty * 4 + i];
#pragma unroll
            for (int j = 0; j < 4; j++) rv[j] = vs[kk][tx * 4 + j];
#pragma unroll
            for (int i = 0; i < 4; i++)
#pragma unroll
                for (int j = 0; j < 4; j++)
                    acc[i][j] = fmaf(rd[i], rv[j], acc[i][j]);
        }
        __syncthreads();
    }

    float* out = g_Cp + ((long)bh * 8 + tc) * (HD * HD);
#pragma unroll
    for (int i = 0; i < 4; i++)
#pragma unroll
        for (int j = 0; j < 4; j++)
            out[(ty * 4 + i) * HD + tx * 4 + j] = acc[i][j];
}

__global__ __launch_bounds__(256)
void context_reduce()
{
    const int bh = blockIdx.x;
    const int b = bh >> 4, h = bh & 15;
    for (int i = threadIdx.x; i < HD * HD; i += 256) {
        float s = 0.f;
#pragma unroll
        for (int c = 0; c < 8; c++)
            s += g_Cp[((long)bh * 8 + c) * (HD * HD) + i];
        const int d = i >> 6;
        g_Cn[(long)bh * (HD * HD) + i] = s / g_Z[b * DIM + h * HD + d];
    }
}

// ---------------------------------------------------------------------------
// Expand: E_b[h*64+d][n] = sum_w Cn[b,h][d][w] * W_out[h*64+w][n]
// ---------------------------------------------------------------------------
__global__ __launch_bounds__(256)
void expand_kernel(const float* __restrict__ w_out)
{
    const int bh = blockIdx.y;
    const int b = bh >> 4;
    const int h = bh & 15;
    const int cb = blockIdx.x * 128;

    __shared__ float cs[64][64];
    __shared__ float ws[64][128];

    const int tid = threadIdx.x;
    for (int i = tid; i < 1024; i += 256) {
        const int r = i >> 4;
        const int c = (i & 15) * 4;
        *(float4*)&cs[r][c] = *(const float4*)(g_Cn + (long)bh * 4096 + r * 64 + c);
    }
    for (int i = tid; i < 2048; i += 256) {
        const int r = i >> 5;
        const int c = (i & 31) * 4;
        *(float4*)&ws[r][c] = *(const float4*)(w_out + (long)(h * HD + r) * DIM + cb + c);
    }
    __syncthreads();

    const int tx = tid & 31;
    const int ty = tid >> 5;

    float acc[8][4];
#pragma unroll
    for (int rr = 0; rr < 8; rr++)
#pragma unroll
        for (int j = 0; j < 4; j++) acc[rr][j] = 0.f;

#pragma unroll 4
    for (int w = 0; w < 64; w++) {
        float4 wv = *(float4*)&ws[w][tx * 4];
#pragma unroll
        for (int rr = 0; rr < 8; rr++) {
            const float cv = cs[ty + rr * 8][w];
            acc[rr][0] = fmaf(cv, wv.x, acc[rr][0]);
            acc[rr][1] = fmaf(cv, wv.y, acc[rr][1]);
            acc[rr][2] = fmaf(cv, wv.z, acc[rr][2]);
            acc[rr][3] = fmaf(cv, wv.w, acc[rr][3]);
        }
    }

#pragma unroll
    for (int rr = 0; rr < 8; rr++) {
        const int row = ty + rr * 8;
        float4 o; o.x = acc[rr][0]; o.y = acc[rr][1]; o.z = acc[rr][2]; o.w = acc[rr][3];
        *(float4*)(g_E + ((long)b * DIM + h * HD + row) * DIM + cb + tx * 4) = o;
    }
}

// ---------------------------------------------------------------------------
extern "C" void kernel_launch(void* const* d_in, const int* in_sizes, int n_in,
                              void* d_out, int out_size)
{
    const float* x     = (const float*)d_in[0];
    const float* z     = (const float*)d_in[1];
    const float* w_q   = (const float*)d_in[2];
    const float* b_q   = (const float*)d_in[3];
    const float* w_kv  = (const float*)d_in[4];
    const float* b_kv  = (const float*)d_in[5];
    const float* w_out = (const float*)d_in[6];
    const float* b_out = (const float*)d_in[7];
    float* out = (float*)d_out;

    float *kv, *E;
    __nv_bfloat16 *zs, *xs, *qs, *wkvs, *wqs, *Es;
    cudaGetSymbolAddress((void**)&kv, g_kv);
    cudaGetSymbolAddress((void**)&E, g_E);
    cudaGetSymbolAddress((void**)&zs, g_zs);
    cudaGetSymbolAddress((void**)&xs, g_xs);
    cudaGetSymbolAddress((void**)&qs, g_qs);
    cudaGetSymbolAddress((void**)&wkvs, g_wkvs);
    cudaGetSymbolAddress((void**)&wqs, g_wqs);
    cudaGetSymbolAddress((void**)&Es, g_Es);

    cudaFuncSetAttribute(gemm_mma, cudaFuncAttributeMaxDynamicSharedMemorySize, GSMEM);

    const int M = BATCH * TLEN;          // 16384
    const long tot4 = (long)M * DIM / 4;

    // 1. weight splits
    { dim3 g(2 * DIM / 32, DIM / 32, 1); split_wt<<<g, 256>>>(w_kv, wkvs, 2 * DIM, 0, 0); }
    { dim3 g(DIM / 32, DIM / 32, 1);     split_wt<<<g, 256>>>(w_q, wqs, DIM, 0, 0); }
    // 2. activation splits
    split_act<<<2048, 256>>>(z, zs, tot4);
    split_act<<<2048, 256>>>(x, xs, tot4);
    // 3. kv = z @ w_kv + b_kv  (fp32 out)
    { dim3 g(2 * DIM / 128, M / 128, 1);
      gemm_mma<<<g, 256, GSMEM>>>(zs, wkvs, b_kv, kv, nullptr, 2 * DIM, 0, 0, 0, 0); }
    // 4. q = x @ w_q + b_q  (split-bf16 out straight into g_qs)
    { dim3 g(DIM / 128, M / 128, 1);
      gemm_mma<<<g, 256, GSMEM>>>(xs, wqs, b_q, nullptr, qs, DIM, 1, 0, 0, 0); }
    // 5. softmax over time on k
    softmax_time_kernel<<<BATCH * (DIM / 32), 256>>>();
    // 6. context
    { dim3 g(BATCH * NH, 8); context_part<<<g, 256>>>(); }
    context_reduce<<<BATCH * NH, 256>>>();
    // 7. E_b = blockdiag(Cn) @ W_out
    { dim3 g(DIM / 128, BATCH * NH); expand_kernel<<<g, 256>>>(w_out); }
    // 8. split E (batched transpose+split)
    { dim3 g(DIM / 32, DIM / 32, BATCH); split_wt<<<g, 256>>>(E, Es, DIM, (long)DIM * DIM, (long)DIM * K3); }
    // 9. out_b = q_b @ E_b + b_out (batched, fp32 out)
    { dim3 g(DIM / 128, TLEN / 128, BATCH);
      gemm_mma<<<g, 256, GSMEM>>>(qs, Es, b_out, out, nullptr, DIM, 0,
                                  (long)TLEN * K3, (long)DIM * K3, (long)TLEN * DIM); }
}